// round 5
// baseline (speedup 1.0000x reference)
#include <cuda_runtime.h>
#include <cuda_bf16.h>

#ifndef D
#define D 128
#endif

// 4 rows per warp. ~130 regs expected — NO reg cap (round 3 proved spills are
// fatal); occupancy comes from 64-thread block quantization (7 blocks/SM).
__global__ __launch_bounds__(64) void sgns_kernel5(
    const int*   __restrict__ x,        // [BS, 1, 3] int32
    const float* __restrict__ tgt_base, // [VOCAB, 128]
    const float* __restrict__ tgt_a,    // [SIDE, 128]
    const float* __restrict__ tgt_b,    // [SIDE, 128]
    const float* __restrict__ ctx_base, // [VOCAB, 128]
    const float* __restrict__ ctx_a,    // [SIDE, 128]
    const float* __restrict__ ctx_b,    // [SIDE, 128]
    const float* __restrict__ tgt_w,    // [3,1]
    const float* __restrict__ ctx_w,    // [3,1]
    float*       __restrict__ out,      // [BS]
    int bs)
{
    const int warp = (blockIdx.x * blockDim.x + threadIdx.x) >> 5;
    const int lane = threadIdx.x & 31;
    const int r0 = warp * 4;
    if (r0 >= bs) return;

    // 12 indices for 4 rows as 3x int4 (warp*48B is 16B-aligned)
    const int4 xi0 = __ldg((const int4*)(x + (size_t)warp * 12) + 0);
    const int4 xi1 = __ldg((const int4*)(x + (size_t)warp * 12) + 1);
    const int4 xi2 = __ldg((const int4*)(x + (size_t)warp * 12) + 2);
    int idx[4][3];
    idx[0][0] = xi0.x; idx[0][1] = xi0.y; idx[0][2] = xi0.z;
    idx[1][0] = xi0.w; idx[1][1] = xi1.x; idx[1][2] = xi1.y;
    idx[2][0] = xi1.z; idx[2][1] = xi1.w; idx[2][2] = xi2.x;
    idx[3][0] = xi2.y; idx[3][1] = xi2.z; idx[3][2] = xi2.w;

    // 24 independent 16B gathers, all issued before dependent math
    float4 tb[4], ta[4], tc[4], cb[4], ca[4], cc[4];
    #pragma unroll
    for (int r = 0; r < 4; r++) {
        tb[r] = __ldg((const float4*)(tgt_base + (size_t)idx[r][0] * D) + lane);
        ta[r] = __ldg((const float4*)(tgt_a    + (size_t)idx[r][1] * D) + lane);
        tc[r] = __ldg((const float4*)(tgt_b    + (size_t)idx[r][2] * D) + lane);
        cb[r] = __ldg((const float4*)(ctx_base + (size_t)idx[r][0] * D) + lane);
        ca[r] = __ldg((const float4*)(ctx_a    + (size_t)idx[r][1] * D) + lane);
        cc[r] = __ldg((const float4*)(ctx_b    + (size_t)idx[r][2] * D) + lane);
    }

    // softmax weights — overlap with gather latency
    float tw0 = __ldg(&tgt_w[0]), tw1 = __ldg(&tgt_w[1]), tw2 = __ldg(&tgt_w[2]);
    float tm  = fmaxf(tw0, fmaxf(tw1, tw2));
    float te0 = __expf(tw0 - tm), te1 = __expf(tw1 - tm), te2 = __expf(tw2 - tm);
    float tinv = __frcp_rn(te0 + te1 + te2);
    float w0 = te0 * tinv, w1 = te1 * tinv, w2 = te2 * tinv;

    float cw0 = __ldg(&ctx_w[0]), cw1 = __ldg(&ctx_w[1]), cw2 = __ldg(&ctx_w[2]);
    float cm  = fmaxf(cw0, fmaxf(cw1, cw2));
    float ce0 = __expf(cw0 - cm), ce1 = __expf(cw1 - cm), ce2 = __expf(cw2 - cm);
    float cinv = __frcp_rn(ce0 + ce1 + ce2);
    float v0 = ce0 * cinv, v1 = ce1 * cinv, v2 = ce2 * cinv;

    float p[4];
    #pragma unroll
    for (int r = 0; r < 4; r++) {
        float tx, cx, acc;
        tx  = w0 * tb[r].x + w1 * ta[r].x + w2 * tc[r].x;
        cx  = v0 * cb[r].x + v1 * ca[r].x + v2 * cc[r].x;
        acc = tx * cx;
        tx  = w0 * tb[r].y + w1 * ta[r].y + w2 * tc[r].y;
        cx  = v0 * cb[r].y + v1 * ca[r].y + v2 * cc[r].y;
        acc += tx * cx;
        tx  = w0 * tb[r].z + w1 * ta[r].z + w2 * tc[r].z;
        cx  = v0 * cb[r].z + v1 * ca[r].z + v2 * cc[r].z;
        acc += tx * cx;
        tx  = w0 * tb[r].w + w1 * ta[r].w + w2 * tc[r].w;
        cx  = v0 * cb[r].w + v1 * ca[r].w + v2 * cc[r].w;
        acc += tx * cx;
        p[r] = acc;
    }

    // 4 reductions pipeline through the SHFL latency
    #pragma unroll
    for (int off = 16; off > 0; off >>= 1) {
        #pragma unroll
        for (int r = 0; r < 4; r++)
            p[r] += __shfl_xor_sync(0xFFFFFFFFu, p[r], off);
    }

    if (lane == 0) {
        float4 s;
        s.x = __frcp_rn(1.0f + __expf(-p[0]));
        s.y = __frcp_rn(1.0f + __expf(-p[1]));
        s.z = __frcp_rn(1.0f + __expf(-p[2]));
        s.w = __frcp_rn(1.0f + __expf(-p[3]));
        if (r0 + 3 < bs) {
            *(float4*)(out + r0) = s;   // r0 multiple of 4 -> 16B aligned
        } else {
            out[r0] = s.x;
            if (r0 + 1 < bs) out[r0 + 1] = s.y;
            if (r0 + 2 < bs) out[r0 + 2] = s.z;
        }
    }
}

extern "C" void kernel_launch(void* const* d_in, const int* in_sizes, int n_in,
                              void* d_out, int out_size)
{
    const int*   x        = (const int*)  d_in[0];
    const float* tgt_base = (const float*)d_in[1];
    const float* tgt_a    = (const float*)d_in[2];
    const float* tgt_b    = (const float*)d_in[3];
    const float* ctx_base = (const float*)d_in[4];
    const float* ctx_a    = (const float*)d_in[5];
    const float* ctx_b    = (const float*)d_in[6];
    const float* tgt_w    = (const float*)d_in[7];
    const float* ctx_w    = (const float*)d_in[8];
    float* out = (float*)d_out;

    const int bs = in_sizes[0] / 3;
    const int threads = 64;
    const int rows_per_block = (threads / 32) * 4;     // 8 rows/block
    const int blocks = (bs + rows_per_block - 1) / rows_per_block;

    sgns_kernel5<<<blocks, threads>>>(x, tgt_base, tgt_a, tgt_b,
                                      ctx_base, ctx_a, ctx_b,
                                      tgt_w, ctx_w, out, bs);
}

// round 6
// speedup vs baseline: 1.0060x; 1.0060x over previous
#include <cuda_runtime.h>
#include <cuda_bf16.h>

#define D 128

struct TIdx { int a0, a1, a2, b0, b1, b2; };

struct TBuf {
    float4 t0b, t0a, t0c, c0b, c0a, c0c;
    float4 t1b, t1a, t1c, c1b, c1a, c1c;
};

__device__ __forceinline__ TIdx load_idx(const int* __restrict__ x, int task)
{
    const int2* p = (const int2*)(x + (size_t)task * 6);
    int2 xa = __ldg(p + 0);
    int2 xb = __ldg(p + 1);
    int2 xc = __ldg(p + 2);
    TIdx r;
    r.a0 = xa.x; r.a1 = xa.y; r.a2 = xb.x;
    r.b0 = xb.y; r.b1 = xc.x; r.b2 = xc.y;
    return r;
}

__device__ __forceinline__ void gather(
    TBuf& b, const TIdx& i, int lane,
    const float* __restrict__ tb_, const float* __restrict__ ta_,
    const float* __restrict__ tc_, const float* __restrict__ cb_,
    const float* __restrict__ ca_, const float* __restrict__ cc_)
{
    b.t0b = __ldg((const float4*)(tb_ + (size_t)i.a0 * D) + lane);
    b.t0a = __ldg((const float4*)(ta_ + (size_t)i.a1 * D) + lane);
    b.t0c = __ldg((const float4*)(tc_ + (size_t)i.a2 * D) + lane);
    b.c0b = __ldg((const float4*)(cb_ + (size_t)i.a0 * D) + lane);
    b.c0a = __ldg((const float4*)(ca_ + (size_t)i.a1 * D) + lane);
    b.c0c = __ldg((const float4*)(cc_ + (size_t)i.a2 * D) + lane);
    b.t1b = __ldg((const float4*)(tb_ + (size_t)i.b0 * D) + lane);
    b.t1a = __ldg((const float4*)(ta_ + (size_t)i.b1 * D) + lane);
    b.t1c = __ldg((const float4*)(tc_ + (size_t)i.b2 * D) + lane);
    b.c1b = __ldg((const float4*)(cb_ + (size_t)i.b0 * D) + lane);
    b.c1a = __ldg((const float4*)(ca_ + (size_t)i.b1 * D) + lane);
    b.c1c = __ldg((const float4*)(cc_ + (size_t)i.b2 * D) + lane);
}

__device__ __forceinline__ void compute_store(
    const TBuf& b, int task, int lane,
    float w0, float w1, float w2, float v0, float v1, float v2,
    float* __restrict__ out)
{
    float tx, cx, p0, p1;
    tx = w0 * b.t0b.x + w1 * b.t0a.x + w2 * b.t0c.x;
    cx = v0 * b.c0b.x + v1 * b.c0a.x + v2 * b.c0c.x;
    p0 = tx * cx;
    tx = w0 * b.t0b.y + w1 * b.t0a.y + w2 * b.t0c.y;
    cx = v0 * b.c0b.y + v1 * b.c0a.y + v2 * b.c0c.y;
    p0 += tx * cx;
    tx = w0 * b.t0b.z + w1 * b.t0a.z + w2 * b.t0c.z;
    cx = v0 * b.c0b.z + v1 * b.c0a.z + v2 * b.c0c.z;
    p0 += tx * cx;
    tx = w0 * b.t0b.w + w1 * b.t0a.w + w2 * b.t0c.w;
    cx = v0 * b.c0b.w + v1 * b.c0a.w + v2 * b.c0c.w;
    p0 += tx * cx;

    tx = w0 * b.t1b.x + w1 * b.t1a.x + w2 * b.t1c.x;
    cx = v0 * b.c1b.x + v1 * b.c1a.x + v2 * b.c1c.x;
    p1 = tx * cx;
    tx = w0 * b.t1b.y + w1 * b.t1a.y + w2 * b.t1c.y;
    cx = v0 * b.c1b.y + v1 * b.c1a.y + v2 * b.c1c.y;
    p1 += tx * cx;
    tx = w0 * b.t1b.z + w1 * b.t1a.z + w2 * b.t1c.z;
    cx = v0 * b.c1b.z + v1 * b.c1a.z + v2 * b.c1c.z;
    p1 += tx * cx;
    tx = w0 * b.t1b.w + w1 * b.t1a.w + w2 * b.t1c.w;
    cx = v0 * b.c1b.w + v1 * b.c1a.w + v2 * b.c1c.w;
    p1 += tx * cx;

    #pragma unroll
    for (int off = 16; off > 0; off >>= 1) {
        p0 += __shfl_xor_sync(0xFFFFFFFFu, p0, off);
        p1 += __shfl_xor_sync(0xFFFFFFFFu, p1, off);
    }

    if (lane == 0) {
        float s0 = __frcp_rn(1.0f + __expf(-p0));
        float s1 = __frcp_rn(1.0f + __expf(-p1));
        *(float2*)(out + (size_t)task * 2) = make_float2(s0, s1);
    }
}

// Persistent, software-pipelined: while stage i computes, stage i+1's gathers
// are in flight. ~130 regs live at peak; cap 146 (64thr x 7 blocks/SM) is
// generous — NOT a round-3-style tight cap.
__global__ __launch_bounds__(64, 7) void sgns_kernel6(
    const int*   __restrict__ x,
    const float* __restrict__ tgt_base, const float* __restrict__ tgt_a,
    const float* __restrict__ tgt_b,    const float* __restrict__ ctx_base,
    const float* __restrict__ ctx_a,    const float* __restrict__ ctx_b,
    const float* __restrict__ tgt_w,    const float* __restrict__ ctx_w,
    float* __restrict__ out, int ntasks)
{
    const int lane   = threadIdx.x & 31;
    const int stride = gridDim.x * (blockDim.x >> 5);
    int task = (blockIdx.x * blockDim.x + threadIdx.x) >> 5;
    if (task >= ntasks) return;

    // softmax weights (uniform, L1-resident)
    float tw0 = __ldg(&tgt_w[0]), tw1 = __ldg(&tgt_w[1]), tw2 = __ldg(&tgt_w[2]);
    float tm  = fmaxf(tw0, fmaxf(tw1, tw2));
    float te0 = __expf(tw0 - tm), te1 = __expf(tw1 - tm), te2 = __expf(tw2 - tm);
    float ti  = __frcp_rn(te0 + te1 + te2);
    const float w0 = te0 * ti, w1 = te1 * ti, w2 = te2 * ti;

    float cw0 = __ldg(&ctx_w[0]), cw1 = __ldg(&ctx_w[1]), cw2 = __ldg(&ctx_w[2]);
    float cm  = fmaxf(cw0, fmaxf(cw1, cw2));
    float ce0 = __expf(cw0 - cm), ce1 = __expf(cw1 - cm), ce2 = __expf(cw2 - cm);
    float ci  = __frcp_rn(ce0 + ce1 + ce2);
    const float v0 = ce0 * ci, v1 = ce1 * ci, v2 = ce2 * ci;

    // ---- pipeline prologue ----
    TIdx iA = load_idx(x, task);
    TBuf A;
    gather(A, iA, lane, tgt_base, tgt_a, tgt_b, ctx_base, ctx_a, ctx_b);

    int next = task + stride;
    TIdx iN = load_idx(x, (next < ntasks) ? next : task);

    TBuf B;
    for (;;) {
        // ---- half 1: stage B = task `next`, retire A = `task` ----
        bool hasB = (next < ntasks);
        if (hasB)
            gather(B, iN, lane, tgt_base, tgt_a, tgt_b, ctx_base, ctx_a, ctx_b);
        int n2 = next + stride;
        iN = load_idx(x, (n2 < ntasks) ? n2 : task);

        compute_store(A, task, lane, w0, w1, w2, v0, v1, v2, out);
        if (!hasB) return;
        task = next; next = n2;

        // ---- half 2: stage A = task `next`, retire B = `task` ----
        bool hasA = (next < ntasks);
        if (hasA)
            gather(A, iN, lane, tgt_base, tgt_a, tgt_b, ctx_base, ctx_a, ctx_b);
        int n3 = next + stride;
        iN = load_idx(x, (n3 < ntasks) ? n3 : task);

        compute_store(B, task, lane, w0, w1, w2, v0, v1, v2, out);
        if (!hasA) return;
        task = next; next = n3;
    }
}

extern "C" void kernel_launch(void* const* d_in, const int* in_sizes, int n_in,
                              void* d_out, int out_size)
{
    const int*   x        = (const int*)  d_in[0];
    const float* tgt_base = (const float*)d_in[1];
    const float* tgt_a    = (const float*)d_in[2];
    const float* tgt_b    = (const float*)d_in[3];
    const float* ctx_base = (const float*)d_in[4];
    const float* ctx_a    = (const float*)d_in[5];
    const float* ctx_b    = (const float*)d_in[6];
    const float* tgt_w    = (const float*)d_in[7];
    const float* ctx_w    = (const float*)d_in[8];
    float* out = (float*)d_out;

    const int bs     = in_sizes[0] / 3;
    const int ntasks = bs / 2;              // 2 rows per task (BS is even)

    const int threads = 64;                  // 2 warps/block
    int blocks = 1024;                       // 2048 warps -> 4 tasks each, fully
                                             // resident at 7 blocks/SM on 148 SMs
    const int max_blocks = (ntasks + 1) / 2;
    if (blocks > max_blocks) blocks = max_blocks;

    sgns_kernel6<<<blocks, threads>>>(x, tgt_base, tgt_a, tgt_b,
                                      ctx_base, ctx_a, ctx_b,
                                      tgt_w, ctx_w, out, ntasks);
}